// round 1
// baseline (speedup 1.0000x reference)
#include <cuda_runtime.h>
#include <cstdint>

// FP4RoundingPerturb:
//   per-32-block e8m0 scale from amax, E2M1 hard quantize + codes,
//   soft ordinal sigmoid weights (output), straight-through y.
//
// Output layout (float32, reference return order, flattened+concatenated):
//   [0,       N)          y
//   [N,       2N)         codes (as float)
//   [2N,      2N+B)       scales (e8m0+127 as float), B = N/32
//   [2N+B,    2N+B+7)     shifted_bounds
//   [2N+B+7,  2N+B+7+8N)  weights

#define TAU_INV 10.0f
#define WARPS_PER_CTA 8

__device__ float g_sb[8];   // shifted bounds
__device__ float g_K[8];    // exp(sb / tau)

__global__ void prep_kernel(const float* __restrict__ delta_raw,
                            const float* __restrict__ bounds_base,
                            float* __restrict__ sb_out) {
    int i = threadIdx.x;
    if (i < 7) {
        float shift = 0.5f * tanhf(delta_raw[0]);
        float sb = bounds_base[i] + shift;
        g_sb[i] = sb;
        g_K[i] = expf(sb * TAU_INV);
        sb_out[i] = sb;
    }
}

__global__ void __launch_bounds__(32 * WARPS_PER_CTA)
fp4_main_kernel(const float* __restrict__ x,
                const float* __restrict__ values_table,
                float* __restrict__ y,
                float* __restrict__ codes,
                float* __restrict__ scales,
                float* __restrict__ weights,
                int n_blocks) {
    __shared__ float s_vt[8];
    __shared__ float s_sb[8];
    __shared__ float s_K[8];
    // per-warp weight transpose buffer: 32 elems x (8 weights, pad to 9)
    __shared__ float s_w[WARPS_PER_CTA][32 * 9];

    int tid = threadIdx.x;
    if (tid < 8)       s_vt[tid]      = values_table[tid];
    else if (tid < 16) s_sb[tid - 8]  = g_sb[tid - 8];
    else if (tid < 24) s_K[tid - 16]  = g_K[tid - 16];
    __syncthreads();

    int warp = tid >> 5;
    int lane = tid & 31;
    int blk = blockIdx.x * WARPS_PER_CTA + warp;   // one 32-elem block per warp
    if (blk >= n_blocks) return;
    int base = blk * 32;

    float xv = x[base + lane];
    float ax = fabsf(xv);

    // warp-wide amax (non-negative floats compare correctly as uints)
    float amax = __uint_as_float(__reduce_max_sync(0xffffffffu, __float_as_uint(ax)));

    // e8m0 = max(ceil(log2(amax/6)), -127), computed exactly
    float d = amax / 6.0f;
    int e;
    if (d > 0.0f) {
        int ee;
        float m = frexpf(d, &ee);        // d = m * 2^ee, m in [0.5, 1)
        e = (m == 0.5f) ? (ee - 1) : ee; // exact ceil(log2(d))
        if (e < -127) e = -127;
    } else {
        e = -127;
    }
    float scale     = ldexpf(1.0f, e);   // handles subnormal 2^-127
    float inv_scale = ldexpf(1.0f, -e);

    if (lane == 0) scales[blk] = (float)(e + 127);

    float xs = xv * inv_scale;           // exact: power-of-two scaling
    float xa = fabsf(xs);

    // sigmoid at each boundary: p_i = 1 / (1 + K_i * exp(-xa/tau))
    float E = __expf(-xa * TAU_INV);
    float p[7];
    int ord = 0;
    #pragma unroll
    for (int i = 0; i < 7; i++) {
        ord += (xa > s_sb[i]) ? 1 : 0;
        p[i] = __fdividef(1.0f, fmaf(s_K[i], E, 1.0f));
    }

    float w[8];
    w[0] = 1.0f - p[0];
    #pragma unroll
    for (int i = 1; i < 7; i++) w[i] = p[i - 1] - p[i];
    w[7] = p[6];
    float sum = 0.0f;
    #pragma unroll
    for (int i = 0; i < 8; i++) { w[i] = fmaxf(w[i], 0.0f); sum += w[i]; }
    float r = __fdividef(1.0f, sum + 1e-8f);
    #pragma unroll
    for (int i = 0; i < 8; i++) w[i] *= r;

    // straight-through forward value = hard E2M1 value
    float v  = s_vt[ord];
    float ys = (xs >= 0.0f) ? v : -v;
    y[base + lane] = ys * scale;

    int sbit = (xs < 0.0f) ? 8 : 0;
    codes[base + lane] = (float)(sbit | ord);

    // weights: stage in SMEM (pad-9: conflict-free stores), then coalesced 128B writes
    float* sw = s_w[warp];
    #pragma unroll
    for (int i = 0; i < 8; i++) sw[lane * 9 + i] = w[i];
    __syncwarp();
    float* wout = weights + (size_t)base * 8;
    #pragma unroll
    for (int j = 0; j < 8; j++) {
        int k = j * 32 + lane;                    // linear index within 256-float group
        wout[k] = sw[(k >> 3) * 9 + (k & 7)];
    }
}

extern "C" void kernel_launch(void* const* d_in, const int* in_sizes, int n_in,
                              void* d_out, int out_size) {
    const float* x      = (const float*)d_in[0];
    const float* delta  = (const float*)d_in[1];
    const float* bounds = (const float*)d_in[2];
    const float* vt     = (const float*)d_in[3];

    int N = in_sizes[0];
    int n_blocks = N / 32;

    float* out     = (float*)d_out;
    float* y       = out;
    float* codes   = out + (size_t)N;
    float* scales  = out + 2 * (size_t)N;
    float* sb_out  = scales + n_blocks;
    float* weights = sb_out + 7;

    prep_kernel<<<1, 32>>>(delta, bounds, sb_out);

    int ctas = (n_blocks + WARPS_PER_CTA - 1) / WARPS_PER_CTA;
    fp4_main_kernel<<<ctas, 32 * WARPS_PER_CTA>>>(x, vt, y, codes, scales, weights, n_blocks);
}

// round 2
// speedup vs baseline: 1.4623x; 1.4623x over previous
#include <cuda_runtime.h>
#include <cstdint>

// FP4RoundingPerturb — output layout (float32, flattened concat):
//   [0,      N)           y
//   [N,      2N)          codes (as float)
//   [2N,     2N+B)        scales (e8m0+127 as float), B=N/32
//   [2N+B,   2N+B+7)      shifted_bounds
//   [2N+B+7, 2N+B+7+8N)   weights   <-- float offset ≡ 3 (mod 4): misaligned!

#define WARPS_PER_CTA 8
// Each warp handles 128 consecutive elements = 4 amax-blocks of 32.
// Each thread handles 4 consecutive elements (float4 load).

__device__ float g_sb[8];   // shifted bounds
__device__ float g_K[8];    // exp(sb / tau)

__global__ void prep_kernel(const float* __restrict__ delta_raw,
                            const float* __restrict__ bounds_base,
                            float* __restrict__ sb_out) {
    int i = threadIdx.x;
    if (i < 7) {
        float shift = 0.5f * tanhf(delta_raw[0]);
        float sb = bounds_base[i] + shift;
        g_sb[i] = sb;
        g_K[i] = __expf(sb * 10.0f);
        sb_out[i] = sb;
    }
}

// XOR swizzle on float4 slots: slot' = (M & ~7) | ((M + (M>>3)) & 7)
// Conflict-free for writer (M = 8*lane + q) and reader (M = 32*j + lane).
__device__ __forceinline__ int swz_slot(int M) {
    return (M & ~7) | ((M + (M >> 3)) & 7);
}
// scalar float position m -> physical float index
__device__ __forceinline__ int swz_f(int m) {
    int M = m >> 2;
    return (swz_slot(M) << 2) | (m & 3);
}

__global__ void __launch_bounds__(32 * WARPS_PER_CTA)
fp4_main(const float4* __restrict__ x4,
         const float* __restrict__ values_table,
         float* __restrict__ y,
         float* __restrict__ codes,
         float* __restrict__ scales,
         float* __restrict__ weights,   // base float offset ≡ 3 (mod 4)
         int n_elems) {
    // Per-warp staging: 256 float4 slots (1024 floats, image shifted by -1 float)
    // + 4 raw floats for boundary elements. 1028 floats = 4112B (16B-aligned stride).
    __shared__ float s_w[WARPS_PER_CTA][1028];

    int tid  = threadIdx.x;
    int warp = tid >> 5;
    int lane = tid & 31;
    int base = (blockIdx.x * WARPS_PER_CTA + warp) * 128;
    if (base >= n_elems) return;

    // per-thread constants
    float vt_reg = values_table[lane & 7];      // for shfl-based table lookup
    float sb0 = g_sb[0], sb1 = g_sb[1], sb2 = g_sb[2], sb3 = g_sb[3],
          sb4 = g_sb[4], sb5 = g_sb[5], sb6 = g_sb[6];
    float K0 = g_K[0], K1 = g_K[1], K2 = g_K[2], K3 = g_K[3],
          K4 = g_K[4], K5 = g_K[5], K6 = g_K[6];

    float4 xv = x4[(base >> 2) + lane];

    // per-32-block amax: 8-lane segmented max-reduce (floats >=0 compare as uints)
    float axm = fmaxf(fmaxf(fabsf(xv.x), fabsf(xv.y)),
                      fmaxf(fabsf(xv.z), fabsf(xv.w)));
    unsigned u = __float_as_uint(axm);
    u = max(u, __shfl_xor_sync(0xffffffffu, u, 1));
    u = max(u, __shfl_xor_sync(0xffffffffu, u, 2));
    u = max(u, __shfl_xor_sync(0xffffffffu, u, 4));
    float amax = __uint_as_float(u);

    // e8m0 = clamp(ceil(log2(amax/6)), -127, inf) via exponent bits (exact)
    float d = amax / 6.0f;
    int bits = __float_as_int(d);
    int e = (bits >> 23) - 127 + ((bits & 0x7fffff) != 0);
    if (bits < 0x00800000)   // subnormal or zero d (never with N(0,1) data)
        e = (d >= 5.8774717541114375e-39f) ? -126 : -127;
    int escl = max(e, -126); // keep scale construction in normal range
    float scale     = __int_as_float((escl + 127) << 23);
    float inv_scale = __int_as_float((127 - escl) << 23);

    if ((lane & 7) == 0)
        scales[(base >> 5) + (lane >> 3)] = (float)(e + 127);

    float* sw = s_w[warp];
    float w[32];
    float yr[4], cr[4];
    float xin[4] = {xv.x, xv.y, xv.z, xv.w};

    #pragma unroll
    for (int c = 0; c < 4; c++) {
        float xs = xin[c] * inv_scale;     // exact power-of-two scaling
        float xa = fabsf(xs);

        // p_i = sigmoid((xa - sb_i)/tau) = 1 / (1 + K_i * exp(-xa/tau))
        float E  = __expf(xa * -10.0f);
        float p0 = __fdividef(1.0f, fmaf(K0, E, 1.0f));
        float p1 = __fdividef(1.0f, fmaf(K1, E, 1.0f));
        float p2 = __fdividef(1.0f, fmaf(K2, E, 1.0f));
        float p3 = __fdividef(1.0f, fmaf(K3, E, 1.0f));
        float p4 = __fdividef(1.0f, fmaf(K4, E, 1.0f));
        float p5 = __fdividef(1.0f, fmaf(K5, E, 1.0f));
        float p6 = __fdividef(1.0f, fmaf(K6, E, 1.0f));

        int ord = (xa > sb0) + (xa > sb1) + (xa > sb2) + (xa > sb3)
                + (xa > sb4) + (xa > sb5) + (xa > sb6);

        // weights (sum telescopes to 1; clip+normalize are no-ops within tol)
        w[8*c + 0] = 1.0f - p0;
        w[8*c + 1] = p0 - p1;
        w[8*c + 2] = p1 - p2;
        w[8*c + 3] = p2 - p3;
        w[8*c + 4] = p3 - p4;
        w[8*c + 5] = p4 - p5;
        w[8*c + 6] = p5 - p6;
        w[8*c + 7] = p6;

        float v = __shfl_sync(0xffffffffu, vt_reg, ord);
        yr[c] = ((xs >= 0.0f) ? v : -v) * scale;
        cr[c] = (float)(((xs < 0.0f) ? 8 : 0) | ord);

        // Stage weights as soon as the needed values exist (shortens w[] lifetimes).
        // Thread's smem float run: positions [32*lane-1, 32*lane+31)  (image shifted -1)
        // float4 q covers w[4q+1 .. 4q+4] at slot M = 8*lane + q.
        if (c == 0) {
            int s0 = swz_slot(8*lane + 0);
            *(float4*)(sw + 4*s0) = make_float4(w[1], w[2], w[3], w[4]);
            sw[(lane == 0) ? 1024 : swz_f(32*lane - 1)] = w[0];
        } else if (c == 1) {
            int s1 = swz_slot(8*lane + 1);
            int s2 = swz_slot(8*lane + 2);
            *(float4*)(sw + 4*s1) = make_float4(w[5],  w[6],  w[7],  w[8]);
            *(float4*)(sw + 4*s2) = make_float4(w[9],  w[10], w[11], w[12]);
        } else if (c == 2) {
            int s3 = swz_slot(8*lane + 3);
            int s4 = swz_slot(8*lane + 4);
            *(float4*)(sw + 4*s3) = make_float4(w[13], w[14], w[15], w[16]);
            *(float4*)(sw + 4*s4) = make_float4(w[17], w[18], w[19], w[20]);
        } else {
            int s5 = swz_slot(8*lane + 5);
            int s6 = swz_slot(8*lane + 6);
            *(float4*)(sw + 4*s5) = make_float4(w[21], w[22], w[23], w[24]);
            *(float4*)(sw + 4*s6) = make_float4(w[25], w[26], w[27], w[28]);
            #pragma unroll
            for (int i = 0; i < 3; i++)
                sw[(lane == 31) ? (1025 + i) : swz_f(32*lane + 28 + i)] = w[29 + i];
        }
    }

    // coalesced vector outputs (both regions 16B-aligned)
    ((float4*)(y + base))[lane]     = make_float4(yr[0], yr[1], yr[2], yr[3]);
    ((float4*)(codes + base))[lane] = make_float4(cr[0], cr[1], cr[2], cr[3]);

    __syncwarp();

    // weights writeback: aligned float4 interior [W+1, W+1021), boundaries scalar
    float* Wp = weights + (size_t)base * 8;
    float4* dst4 = (float4*)(Wp + 1);   // (2N+B+8 + base*8) ≡ 0 mod 4 -> aligned
    #pragma unroll
    for (int j = 0; j < 8; j++) {
        int idx = 32*j + lane;
        if (idx < 255) {
            int slot = swz_slot(idx);
            dst4[idx] = *(const float4*)(sw + 4*slot);
        }
    }
    if (lane < 4) {
        float val = sw[1024 + lane];
        Wp[(lane == 0) ? 0 : (1020 + lane)] = val;
    }
}

extern "C" void kernel_launch(void* const* d_in, const int* in_sizes, int n_in,
                              void* d_out, int out_size) {
    const float* x      = (const float*)d_in[0];
    const float* delta  = (const float*)d_in[1];
    const float* bounds = (const float*)d_in[2];
    const float* vt     = (const float*)d_in[3];

    int N = in_sizes[0];
    int n_blocks = N / 32;

    float* out     = (float*)d_out;
    float* y       = out;
    float* codes   = out + (size_t)N;
    float* scales  = out + 2 * (size_t)N;
    float* sb_out  = scales + n_blocks;
    float* weights = sb_out + 7;

    prep_kernel<<<1, 32>>>(delta, bounds, sb_out);

    int elems_per_cta = 128 * WARPS_PER_CTA;
    int ctas = (N + elems_per_cta - 1) / elems_per_cta;
    fp4_main<<<ctas, 32 * WARPS_PER_CTA>>>((const float4*)x, vt, y, codes,
                                           scales, weights, N);
}